// round 8
// baseline (speedup 1.0000x reference)
#include <cuda_runtime.h>
#include <cuda_pipeline.h>
#include <math.h>

#define NC   21
#define HW   (512 * 512)          // 2^18
#define NB   8
#define NPIX (NB * HW)            // 2,097,152
#define TPB  256
#define PPT  4                    // pixels per thread (float4)
#define NBLK (NPIX / (TPB * PPT)) // 2048
#define DEPTH 4                   // cp.async pipeline stages

// Allocation-free scratch; zero at module load, reset by the last block after
// consumption so every call / graph replay stays deterministic.
__device__ float        g_cls_sum[NC];
__device__ int          g_cls_cnt[NC];
__device__ unsigned int g_done;

__global__ __launch_bounds__(TPB, 5)
void cbfocal_fused_kernel(const float* __restrict__ pred,
                          const float* __restrict__ target,
                          float* __restrict__ out) {
    // Per-thread-private staging: thread t only ever touches slot [stage][t],
    // so no __syncthreads is needed inside the channel pipeline.
    __shared__ float4 bp[DEPTH][TPB];
    __shared__ float4 bt[DEPTH][TPB];
    __shared__ float  s_sum[NC];
    __shared__ int    s_cnt[NC];
    __shared__ bool   s_last;

    int t = threadIdx.x;
    if (t < NC) { s_sum[t] = 0.0f; s_cnt[t] = 0; }
    __syncthreads();

    // 4 consecutive pixels per thread; all share the same batch index.
    long base = ((long)blockIdx.x * TPB + t) * PPT;
    int  b    = (int)(base >> 18);
    int  hw   = (int)(base & (HW - 1));     // multiple of 4 -> 16B aligned

    const float4* pp = (const float4*)(pred   + (((long)b * NC) << 18) + hw);
    const float4* tp = (const float4*)(target + (((long)b * NC) << 18) + hw);
    const long CSTRIDE4 = HW / 4;           // float4 per channel

    // Online sum-of-exp (inputs ~N(0,1): fp32-safe without max subtraction).
    float4 s   = make_float4(0.f, 0.f, 0.f, 0.f);
    float4 vc  = make_float4(0.f, 0.f, 0.f, 0.f);
    int4   cls = make_int4(0, 0, 0, 0);

    // Prologue: prefetch first DEPTH-1 channels.
    #pragma unroll
    for (int c = 0; c < DEPTH - 1; c++) {
        __pipeline_memcpy_async(&bp[c][t], pp + (long)c * CSTRIDE4, 16);
        __pipeline_memcpy_async(&bt[c][t], tp + (long)c * CSTRIDE4, 16);
        __pipeline_commit();
    }

    #pragma unroll
    for (int c = 0; c < NC; c++) {
        int cn = c + DEPTH - 1;
        if (cn < NC) {
            __pipeline_memcpy_async(&bp[cn % DEPTH][t], pp + (long)cn * CSTRIDE4, 16);
            __pipeline_memcpy_async(&bt[cn % DEPTH][t], tp + (long)cn * CSTRIDE4, 16);
        }
        __pipeline_commit();                 // empty groups in the tail keep
        __pipeline_wait_prior(DEPTH - 1);    // the group arithmetic exact

        float4 pv = bp[c % DEPTH][t];
        float4 tv = bt[c % DEPTH][t];

        s.x += __expf(pv.x);
        s.y += __expf(pv.y);
        s.z += __expf(pv.z);
        s.w += __expf(pv.w);
        if (tv.x > 0.5f) { cls.x = c; vc.x = pv.x; }
        if (tv.y > 0.5f) { cls.y = c; vc.y = pv.y; }
        if (tv.z > 0.5f) { cls.z = c; vc.z = pv.z; }
        if (tv.w > 0.5f) { cls.w = c; vc.w = pv.w; }
    }

    {
        float lp, p, om;
        lp = vc.x - __logf(s.x); p = __expf(lp); om = 1.f - p;
        atomicAdd(&s_sum[cls.x], om * om * lp); atomicAdd(&s_cnt[cls.x], 1);
        lp = vc.y - __logf(s.y); p = __expf(lp); om = 1.f - p;
        atomicAdd(&s_sum[cls.y], om * om * lp); atomicAdd(&s_cnt[cls.y], 1);
        lp = vc.z - __logf(s.z); p = __expf(lp); om = 1.f - p;
        atomicAdd(&s_sum[cls.z], om * om * lp); atomicAdd(&s_cnt[cls.z], 1);
        lp = vc.w - __logf(s.w); p = __expf(lp); om = 1.f - p;
        atomicAdd(&s_sum[cls.w], om * om * lp); atomicAdd(&s_cnt[cls.w], 1);
    }
    __syncthreads();

    if (t < NC) {
        atomicAdd(&g_cls_sum[t], s_sum[t]);
        atomicAdd(&g_cls_cnt[t], s_cnt[t]);
    }

    // Last-block epilogue: weighted reduction + reset.
    __threadfence();
    if (t == 0) {
        unsigned int prev = atomicAdd(&g_done, 1u);
        s_last = (prev == (unsigned int)(gridDim.x - 1));
    }
    __syncthreads();

    if (s_last && t < 32) {
        const double n    = (double)NPIX;
        const double beta = (n - 1.0) / n;

        double val = 0.0;
        if (t < NC) {
            double w = (1.0 - beta) / (1.0 - pow(beta, (double)g_cls_cnt[t]) + 1e-6);
            val = w * (double)g_cls_sum[t];
        }
        #pragma unroll
        for (int o = 16; o > 0; o >>= 1) {
            val += __shfl_down_sync(0xffffffffu, val, o);
        }
        if (t < NC) { g_cls_sum[t] = 0.0f; g_cls_cnt[t] = 0; }
        if (t == 0) {
            g_done = 0u;
            out[0] = (float)(-val / n);
        }
    }
}

extern "C" void kernel_launch(void* const* d_in, const int* in_sizes, int n_in,
                              void* d_out, int out_size) {
    const float* pred   = (const float*)d_in[0];
    const float* target = (const float*)d_in[1];
    cbfocal_fused_kernel<<<NBLK, TPB>>>(pred, target, (float*)d_out);
}

// round 11
// speedup vs baseline: 1.0005x; 1.0005x over previous
#include <cuda_runtime.h>
#include <math.h>

#define NC   21
#define HW   (512 * 512)          // 2^18
#define NB   8
#define NPIX (NB * HW)            // 2,097,152
#define TPB  256
#define NBLK (NPIX / TPB)         // 8192, one pixel per thread
#define GRP  7                    // channels per load batch (21 = 3*7)

// Allocation-free scratch; zero at module load, reset by the last block after
// consumption so every call / graph replay stays deterministic.
__device__ float        g_cls_sum[NC];
__device__ int          g_cls_cnt[NC];
__device__ unsigned int g_done;

__global__ __launch_bounds__(TPB, 5)
void cbfocal_fused_kernel(const float* __restrict__ pred,
                          const float* __restrict__ target,
                          float* __restrict__ out) {
    __shared__ float s_sum[NC];
    __shared__ int   s_cnt[NC];
    __shared__ bool  s_last;

    int t = threadIdx.x;
    if (t < NC) { s_sum[t] = 0.0f; s_cnt[t] = 0; }
    __syncthreads();

    // One pixel per thread — the R1 access pattern that measured ~6.4 TB/s.
    long i  = (long)blockIdx.x * TPB + t;
    int  b  = (int)(i >> 18);
    int  hw = (int)(i & (HW - 1));

    const float* pp = pred   + (((long)b * NC) << 18) + hw;
    const float* tp = target + (((long)b * NC) << 18) + hw;

    // Online sum-of-exp (inputs ~N(0,1): fp32-safe without max subtraction).
    float s   = 0.0f;
    float vc  = 0.0f;
    int   cls = 0;

    // 3 batches of 7 channels: issue all 14 scalar loads before consuming.
    #pragma unroll
    for (int g = 0; g < NC / GRP; g++) {
        float pv[GRP], tv[GRP];
        #pragma unroll
        for (int j = 0; j < GRP; j++)
            pv[j] = pp[(long)(g * GRP + j) << 18];
        #pragma unroll
        for (int j = 0; j < GRP; j++)
            tv[j] = tp[(long)(g * GRP + j) << 18];

        #pragma unroll
        for (int j = 0; j < GRP; j++) {
            int c = g * GRP + j;
            s += __expf(pv[j]);
            if (tv[j] > 0.5f) { cls = c; vc = pv[j]; }
        }
    }

    {
        float lp = vc - __logf(s);
        float p  = __expf(lp);
        float om = 1.0f - p;
        atomicAdd(&s_sum[cls], om * om * lp);
        atomicAdd(&s_cnt[cls], 1);
    }
    __syncthreads();

    if (t < NC) {
        atomicAdd(&g_cls_sum[t], s_sum[t]);
        atomicAdd(&g_cls_cnt[t], s_cnt[t]);
    }

    // Last-block epilogue: weighted reduction + reset.
    __threadfence();
    if (t == 0) {
        unsigned int prev = atomicAdd(&g_done, 1u);
        s_last = (prev == (unsigned int)(gridDim.x - 1));
    }
    __syncthreads();

    if (s_last && t < 32) {
        const double n    = (double)NPIX;
        const double beta = (n - 1.0) / n;

        double val = 0.0;
        if (t < NC) {
            double w = (1.0 - beta) / (1.0 - pow(beta, (double)g_cls_cnt[t]) + 1e-6);
            val = w * (double)g_cls_sum[t];
        }
        #pragma unroll
        for (int o = 16; o > 0; o >>= 1) {
            val += __shfl_down_sync(0xffffffffu, val, o);
        }
        if (t < NC) { g_cls_sum[t] = 0.0f; g_cls_cnt[t] = 0; }
        if (t == 0) {
            g_done = 0u;
            out[0] = (float)(-val / n);
        }
    }
}

extern "C" void kernel_launch(void* const* d_in, const int* in_sizes, int n_in,
                              void* d_out, int out_size) {
    const float* pred   = (const float*)d_in[0];
    const float* target = (const float*)d_in[1];
    cbfocal_fused_kernel<<<NBLK, TPB>>>(pred, target, (float*)d_out);
}